// round 3
// baseline (speedup 1.0000x reference)
#include <cuda_runtime.h>
#include <math.h>

#define N_NODES 50000
#define E_RAW   400000
#define E_TOT   (E_RAW + N_NODES)   // 450000 with self loops
#define IN_DIM  128
#define H1      4
#define C1      64
#define F1      256                 // H1*C1
#define C2      64
#define OUT_DIM 3
#define NEG_SLOPE 0.2f
#define EPSV    1e-16f

// ---------------- scratch (static device globals; no allocation) ----------------
__device__ float g_h1[N_NODES * F1];    // x @ W1
__device__ float g_out1[N_NODES * F1];  // layer-1 aggregation, then elu(.+b1) in place
__device__ float g_as1[N_NODES * H1];
__device__ float g_ad1[N_NODES * H1];
__device__ float g_m1[N_NODES * H1];
__device__ float g_d1[N_NODES * H1];
__device__ float g_e1[E_TOT * H1];

__device__ float g_h2[N_NODES * C2];    // layer-2 linear
__device__ float g_out2[N_NODES * C2];
__device__ float g_as2[N_NODES];
__device__ float g_ad2[N_NODES];
__device__ float g_m2[N_NODES];
__device__ float g_d2[N_NODES];
__device__ float g_e2[E_TOT];

__device__ int g_src[E_TOT];
__device__ int g_dst[E_TOT];
__device__ int g_is64;

// ---------------- helpers ----------------
__device__ __forceinline__ void atomicMaxF(float* addr, float v) {
    if (v >= 0.f) atomicMax((int*)addr, __float_as_int(v));
    else          atomicMin((unsigned int*)addr, __float_as_uint(v));
}

__device__ __forceinline__ float eluf(float x) {
    return x > 0.f ? x : expm1f(x);
}

// ---------------- edge index dtype detect + convert ----------------
// If edge_index is int64 (little endian), the high 32-bit word of each value is 0
// (ids < 50000). If it is int32, odd words are random node ids (mostly nonzero).
__global__ void detect_kernel(const unsigned int* __restrict__ ei32) {
    if (threadIdx.x == 0 && blockIdx.x == 0) {
        unsigned int ornz = 0;
        #pragma unroll
        for (int i = 0; i < 64; i++) ornz |= ei32[2 * i + 1];
        g_is64 = (ornz == 0u) ? 1 : 0;
    }
}

__global__ void convert_kernel(const void* __restrict__ ei) {
    int e = blockIdx.x * blockDim.x + threadIdx.x;
    if (e >= E_TOT) return;
    if (e >= E_RAW) { g_src[e] = g_dst[e] = e - E_RAW; return; }
    if (g_is64) {
        const long long* p = (const long long*)ei;
        g_src[e] = (int)p[e];
        g_dst[e] = (int)p[E_RAW + e];
    } else {
        const int* p = (const int*)ei;
        g_src[e] = p[e];
        g_dst[e] = p[E_RAW + e];
    }
}

// ---------------- init ----------------
__global__ void init_kernel() {
    int idx = blockIdx.x * blockDim.x + threadIdx.x;
    if (idx < N_NODES * F1) g_out1[idx] = 0.f;
    if (idx < N_NODES * C2) g_out2[idx] = 0.f;
    if (idx < N_NODES * H1) { g_m1[idx] = -INFINITY; g_d1[idx] = 0.f; }
    if (idx < N_NODES)      { g_m2[idx] = -INFINITY; g_d2[idx] = 0.f; }
}

// ---------------- tiled GEMM: C[M,N] = A[M,K] @ B[K,N] ----------------
#define BM 64
#define BN 64
#define BK 16
__global__ __launch_bounds__(256) void gemm_kernel(const float* __restrict__ A,
                                                   const float* __restrict__ B,
                                                   float* __restrict__ C,
                                                   int M, int K, int N) {
    __shared__ float As[BK][BM + 1];
    __shared__ float Bs[BK][BN + 1];
    const int tid = threadIdx.x;
    const int tx = tid & 15, ty = tid >> 4;
    const int by = blockIdx.y * BM, bx = blockIdx.x * BN;

    float acc[4][4] = {};
    for (int k0 = 0; k0 < K; k0 += BK) {
        #pragma unroll
        for (int i = tid; i < BM * BK; i += 256) {
            int r = i >> 4, c = i & 15;
            int row = by + r;
            As[c][r] = (row < M) ? A[(long)row * K + k0 + c] : 0.f;
        }
        #pragma unroll
        for (int i = tid; i < BK * BN; i += 256) {
            int r = i >> 6, c = i & 63;
            Bs[r][c] = B[(long)(k0 + r) * N + bx + c];
        }
        __syncthreads();
        #pragma unroll
        for (int kk = 0; kk < BK; kk++) {
            float a[4], b[4];
            #pragma unroll
            for (int m = 0; m < 4; m++) a[m] = As[kk][ty * 4 + m];
            #pragma unroll
            for (int n = 0; n < 4; n++) b[n] = Bs[kk][tx * 4 + n];
            #pragma unroll
            for (int m = 0; m < 4; m++)
                #pragma unroll
                for (int n = 0; n < 4; n++)
                    acc[m][n] = fmaf(a[m], b[n], acc[m][n]);
        }
        __syncthreads();
    }
    #pragma unroll
    for (int m = 0; m < 4; m++) {
        int row = by + ty * 4 + m;
        if (row < M) {
            #pragma unroll
            for (int n = 0; n < 4; n++)
                C[(long)row * N + bx + tx * 4 + n] = acc[m][n];
        }
    }
}

// ---------------- attention scores ----------------
__global__ void attscore1_kernel(const float* __restrict__ att_src,
                                 const float* __restrict__ att_dst) {
    int idx = blockIdx.x * blockDim.x + threadIdx.x;
    if (idx >= N_NODES * H1) return;
    int n = idx / H1, h = idx % H1;
    const float* hp = &g_h1[(long)n * F1 + h * C1];
    float s = 0.f, d = 0.f;
    #pragma unroll
    for (int c = 0; c < C1; c++) {
        float v = hp[c];
        s = fmaf(v, att_src[h * C1 + c], s);
        d = fmaf(v, att_dst[h * C1 + c], d);
    }
    g_as1[idx] = s;
    g_ad1[idx] = d;
}

__global__ void attscore2_kernel(const float* __restrict__ att_src,
                                 const float* __restrict__ att_dst) {
    int n = blockIdx.x * blockDim.x + threadIdx.x;
    if (n >= N_NODES) return;
    const float* hp = &g_h2[(long)n * C2];
    float s = 0.f, d = 0.f;
    #pragma unroll
    for (int c = 0; c < C2; c++) {
        float v = hp[c];
        s = fmaf(v, att_src[c], s);
        d = fmaf(v, att_dst[c], d);
    }
    g_as2[n] = s;
    g_ad2[n] = d;
}

// ---------------- layer-1 edge passes ----------------
__global__ void edge1_a() {
    int e = blockIdx.x * blockDim.x + threadIdx.x;
    if (e >= E_TOT) return;
    int s = g_src[e], d = g_dst[e];
    #pragma unroll
    for (int h = 0; h < H1; h++) {
        float v = g_as1[s * H1 + h] + g_ad1[d * H1 + h];
        v = v > 0.f ? v : NEG_SLOPE * v;
        g_e1[(long)e * H1 + h] = v;
        atomicMaxF(&g_m1[d * H1 + h], v);
    }
}

__global__ void edge1_b() {
    int e = blockIdx.x * blockDim.x + threadIdx.x;
    if (e >= E_TOT) return;
    int d = g_dst[e];
    #pragma unroll
    for (int h = 0; h < H1; h++) {
        float ex = expf(g_e1[(long)e * H1 + h] - g_m1[d * H1 + h]);
        g_e1[(long)e * H1 + h] = ex;
        atomicAdd(&g_d1[d * H1 + h], ex);
    }
}

__global__ __launch_bounds__(256) void edge1_c() {
    int e = (blockIdx.x * blockDim.x + threadIdx.x) >> 5;
    int lane = threadIdx.x & 31;
    if (e >= E_TOT) return;
    int s = g_src[e], d = g_dst[e];
    float al[H1];
    #pragma unroll
    for (int h = 0; h < H1; h++)
        al[h] = g_e1[(long)e * H1 + h] / (g_d1[d * H1 + h] + EPSV);
    const float* hs = &g_h1[(long)s * F1];
    float* od = &g_out1[(long)d * F1];
    #pragma unroll
    for (int f = lane; f < F1; f += 32)
        atomicAdd(&od[f], hs[f] * al[f >> 6]);
}

// elu(out1 + b1) in place -> becomes layer-2 input
__global__ void elu_bias1(const float* __restrict__ b1) {
    int idx = blockIdx.x * blockDim.x + threadIdx.x;
    if (idx >= N_NODES * F1) return;
    float v = g_out1[idx] + b1[idx & (F1 - 1)];
    g_out1[idx] = eluf(v);
}

// ---------------- layer-2 edge passes (H=1) ----------------
__global__ void edge2_a() {
    int e = blockIdx.x * blockDim.x + threadIdx.x;
    if (e >= E_TOT) return;
    int s = g_src[e], d = g_dst[e];
    float v = g_as2[s] + g_ad2[d];
    v = v > 0.f ? v : NEG_SLOPE * v;
    g_e2[e] = v;
    atomicMaxF(&g_m2[d], v);
}

__global__ void edge2_b() {
    int e = blockIdx.x * blockDim.x + threadIdx.x;
    if (e >= E_TOT) return;
    int d = g_dst[e];
    float ex = expf(g_e2[e] - g_m2[d]);
    g_e2[e] = ex;
    atomicAdd(&g_d2[d], ex);
}

__global__ __launch_bounds__(256) void edge2_c() {
    int e = (blockIdx.x * blockDim.x + threadIdx.x) >> 5;
    int lane = threadIdx.x & 31;
    if (e >= E_TOT) return;
    int s = g_src[e], d = g_dst[e];
    float al = g_e2[e] / (g_d2[d] + EPSV);
    const float* hs = &g_h2[(long)s * C2];
    float* od = &g_out2[(long)d * C2];
    #pragma unroll
    for (int f = lane; f < C2; f += 32)
        atomicAdd(&od[f], hs[f] * al);
}

// ---------------- final: elu(out2+b2) @ Wout + bout ----------------
__global__ void final_kernel(const float* __restrict__ b2,
                             const float* __restrict__ Wout,
                             const float* __restrict__ bout,
                             float* __restrict__ out) {
    int n = blockIdx.x * blockDim.x + threadIdx.x;
    if (n >= N_NODES) return;
    float acc0 = bout[0], acc1 = bout[1], acc2 = bout[2];
    const float* op = &g_out2[(long)n * C2];
    #pragma unroll
    for (int c = 0; c < C2; c++) {
        float v = eluf(op[c] + b2[c]);
        acc0 = fmaf(v, Wout[c * 3 + 0], acc0);
        acc1 = fmaf(v, Wout[c * 3 + 1], acc1);
        acc2 = fmaf(v, Wout[c * 3 + 2], acc2);
    }
    out[n * 3 + 0] = acc0;
    out[n * 3 + 1] = acc1;
    out[n * 3 + 2] = acc2;
}

// ---------------- launch ----------------
extern "C" void kernel_launch(void* const* d_in, const int* in_sizes, int n_in,
                              void* d_out, int out_size) {
    const float* x        = (const float*)d_in[0];
    const void*  ei       = d_in[1];
    const float* W1       = (const float*)d_in[2];
    const float* att_src1 = (const float*)d_in[3];
    const float* att_dst1 = (const float*)d_in[4];
    const float* b1       = (const float*)d_in[5];
    const float* W2       = (const float*)d_in[6];
    const float* att_src2 = (const float*)d_in[7];
    const float* att_dst2 = (const float*)d_in[8];
    const float* b2       = (const float*)d_in[9];
    const float* Wout     = (const float*)d_in[10];
    const float* bout     = (const float*)d_in[11];
    float* out = (float*)d_out;

    float *p_h1, *p_out1, *p_h2;
    cudaGetSymbolAddress((void**)&p_h1,   g_h1);
    cudaGetSymbolAddress((void**)&p_out1, g_out1);
    cudaGetSymbolAddress((void**)&p_h2,   g_h2);

    const int T = 256;

    // edge index dtype detect + convert to int32 src/dst (with self loops)
    detect_kernel<<<1, 32>>>((const unsigned int*)ei);
    convert_kernel<<<(E_TOT + T - 1) / T, T>>>(ei);

    // init accumulators
    init_kernel<<<(N_NODES * F1 + T - 1) / T, T>>>();

    // layer 1
    {
        dim3 grid(F1 / BN, (N_NODES + BM - 1) / BM);
        gemm_kernel<<<grid, 256>>>(x, W1, p_h1, N_NODES, IN_DIM, F1);
    }
    attscore1_kernel<<<(N_NODES * H1 + T - 1) / T, T>>>(att_src1, att_dst1);
    edge1_a<<<(E_TOT + T - 1) / T, T>>>();
    edge1_b<<<(E_TOT + T - 1) / T, T>>>();
    edge1_c<<<(E_TOT * 32 + T - 1) / T, T>>>();
    elu_bias1<<<(N_NODES * F1 + T - 1) / T, T>>>(b1);

    // layer 2
    {
        dim3 grid(C2 / BN, (N_NODES + BM - 1) / BM);
        gemm_kernel<<<grid, 256>>>(p_out1, W2, p_h2, N_NODES, F1, C2);
    }
    attscore2_kernel<<<(N_NODES + T - 1) / T, T>>>(att_src2, att_dst2);
    edge2_a<<<(E_TOT + T - 1) / T, T>>>();
    edge2_b<<<(E_TOT + T - 1) / T, T>>>();
    edge2_c<<<(E_TOT * 32 + T - 1) / T, T>>>();

    // output head
    final_kernel<<<(N_NODES + T - 1) / T, T>>>(b2, Wout, bout, out);
}

// round 4
// speedup vs baseline: 1.4733x; 1.4733x over previous
#include <cuda_runtime.h>
#include <math.h>
#include <stdint.h>

#define N_NODES 50000
#define E_RAW   400000
#define E_TOT   (E_RAW + N_NODES)   // 450000 with self loops
#define IN_DIM  128
#define H1      4
#define C1      64
#define F1      256                 // H1*C1
#define C2      64
#define OUT_DIM 3
#define NEG_SLOPE 0.2f
#define EPSV    1e-16f

// ---------------- scratch (static device globals; no allocation) ----------------
__device__ __align__(16) float g_h1[N_NODES * F1];    // x @ W1
__device__ __align__(16) float g_out1[N_NODES * F1];  // layer-1 agg, then elu(.+b1)
__device__ __align__(16) float g_as1[N_NODES * H1];
__device__ __align__(16) float g_ad1[N_NODES * H1];
__device__ __align__(16) float g_d1[N_NODES * H1];
__device__ __align__(16) float g_e1[E_TOT * H1];

__device__ __align__(16) float g_h2[N_NODES * C2];    // layer-2 linear
__device__ __align__(16) float g_out2[N_NODES * C2];
__device__ float g_as2[N_NODES];
__device__ float g_ad2[N_NODES];
__device__ float g_d2[N_NODES];
__device__ float g_e2[E_TOT];

__device__ int g_src[E_TOT];
__device__ int g_dst[E_TOT];
__device__ int g_is64;

// ---------------- helpers ----------------
__device__ __forceinline__ float eluf(float x) {
    return x > 0.f ? x : expm1f(x);
}

__device__ __forceinline__ void red_add_v4(float* ptr, float4 v) {
    unsigned long long g;
    asm volatile("cvta.to.global.u64 %0, %1;" : "=l"(g) : "l"(ptr));
    asm volatile("red.global.v4.f32.add [%0], {%1,%2,%3,%4};"
                 :: "l"(g), "f"(v.x), "f"(v.y), "f"(v.z), "f"(v.w) : "memory");
}

// ---------------- edge index dtype detect + convert ----------------
__global__ void detect_kernel(const unsigned int* __restrict__ ei32) {
    if (threadIdx.x == 0 && blockIdx.x == 0) {
        unsigned int ornz = 0;
        #pragma unroll
        for (int i = 0; i < 64; i++) ornz |= ei32[2 * i + 1];
        g_is64 = (ornz == 0u) ? 1 : 0;
    }
}

__global__ void convert_kernel(const void* __restrict__ ei) {
    int e = blockIdx.x * blockDim.x + threadIdx.x;
    if (e >= E_TOT) return;
    if (e >= E_RAW) { g_src[e] = g_dst[e] = e - E_RAW; return; }
    if (g_is64) {
        const long long* p = (const long long*)ei;
        g_src[e] = (int)p[e];
        g_dst[e] = (int)p[E_RAW + e];
    } else {
        const int* p = (const int*)ei;
        g_src[e] = p[e];
        g_dst[e] = p[E_RAW + e];
    }
}

// ---------------- init ----------------
__global__ void init_kernel() {
    int idx = blockIdx.x * blockDim.x + threadIdx.x;
    if (idx < N_NODES * F1) g_out1[idx] = 0.f;
    if (idx < N_NODES * C2) g_out2[idx] = 0.f;
    if (idx < N_NODES * H1) g_d1[idx] = 0.f;
    if (idx < N_NODES)      g_d2[idx] = 0.f;
}

// ---------------- tiled GEMM: C[M,N] = A[M,K] @ B[K,N] ----------------
// 128x64 tile, 256 threads, 8x4 microtile, float4 smem loads.
// K multiple of 16, N multiple of 64.
#define GBM 128
#define GBN 64
#define GBK 16
__global__ __launch_bounds__(256) void gemm_kernel(const float* __restrict__ A,
                                                   const float* __restrict__ B,
                                                   float* __restrict__ C,
                                                   int M, int K, int N) {
    __shared__ float As[GBK][GBM];   // transposed A tile
    __shared__ float Bs[GBK][GBN];
    const int tid = threadIdx.x;
    const int tx = tid & 15;         // col group (0..15) -> 4 cols
    const int ty = tid >> 4;         // row group (0..15) -> 8 rows
    const int by = blockIdx.y * GBM, bx = blockIdx.x * GBN;

    float acc[8][4] = {};
    for (int k0 = 0; k0 < K; k0 += GBK) {
        // A tile: 128 rows x 16 cols = 512 float4, 2 per thread
        #pragma unroll
        for (int i = 0; i < 2; i++) {
            int idx = tid + i * 256;
            int r = idx >> 2, c4 = (idx & 3) * 4;
            int row = by + r;
            float4 v = make_float4(0.f, 0.f, 0.f, 0.f);
            if (row < M) v = *(const float4*)&A[(long)row * K + k0 + c4];
            As[c4 + 0][r] = v.x;
            As[c4 + 1][r] = v.y;
            As[c4 + 2][r] = v.z;
            As[c4 + 3][r] = v.w;
        }
        // B tile: 16 rows x 64 cols = 256 float4, 1 per thread
        {
            int r = tid >> 4, c4 = (tid & 15) * 4;
            *(float4*)&Bs[r][c4] = *(const float4*)&B[(long)(k0 + r) * N + bx + c4];
        }
        __syncthreads();
        #pragma unroll
        for (int kk = 0; kk < GBK; kk++) {
            float4 a0 = *(const float4*)&As[kk][ty * 8];
            float4 a1 = *(const float4*)&As[kk][ty * 8 + 4];
            float4 b  = *(const float4*)&Bs[kk][tx * 4];
            float a[8] = {a0.x, a0.y, a0.z, a0.w, a1.x, a1.y, a1.z, a1.w};
            float bb[4] = {b.x, b.y, b.z, b.w};
            #pragma unroll
            for (int m = 0; m < 8; m++)
                #pragma unroll
                for (int n = 0; n < 4; n++)
                    acc[m][n] = fmaf(a[m], bb[n], acc[m][n]);
        }
        __syncthreads();
    }
    #pragma unroll
    for (int m = 0; m < 8; m++) {
        int row = by + ty * 8 + m;
        if (row < M) {
            float4 v = make_float4(acc[m][0], acc[m][1], acc[m][2], acc[m][3]);
            *(float4*)&C[(long)row * N + bx + tx * 4] = v;
        }
    }
}

// ---------------- attention scores ----------------
__global__ void attscore1_kernel(const float* __restrict__ att_src,
                                 const float* __restrict__ att_dst) {
    int idx = blockIdx.x * blockDim.x + threadIdx.x;
    if (idx >= N_NODES * H1) return;
    int n = idx / H1, h = idx % H1;
    const float* hp = &g_h1[(long)n * F1 + h * C1];
    float s = 0.f, d = 0.f;
    #pragma unroll
    for (int c = 0; c < C1; c++) {
        float v = hp[c];
        s = fmaf(v, att_src[h * C1 + c], s);
        d = fmaf(v, att_dst[h * C1 + c], d);
    }
    g_as1[idx] = s;
    g_ad1[idx] = d;
}

__global__ void attscore2_kernel(const float* __restrict__ att_src,
                                 const float* __restrict__ att_dst) {
    int n = blockIdx.x * blockDim.x + threadIdx.x;
    if (n >= N_NODES) return;
    const float* hp = &g_h2[(long)n * C2];
    float s = 0.f, d = 0.f;
    #pragma unroll
    for (int c = 0; c < C2; c++) {
        float v = hp[c];
        s = fmaf(v, att_src[c], s);
        d = fmaf(v, att_dst[c], d);
    }
    g_as2[n] = s;
    g_ad2[n] = d;
}

// ---------------- layer-1: fused leakyrelu+exp+denom (no max: shift-invariant) ----------------
__global__ void edge1_ab() {
    int e = blockIdx.x * blockDim.x + threadIdx.x;
    if (e >= E_TOT) return;
    int s = g_src[e], d = g_dst[e];
    float4 as = *(const float4*)&g_as1[s * H1];
    float4 ad = *(const float4*)&g_ad1[d * H1];
    float v[4] = {as.x + ad.x, as.y + ad.y, as.z + ad.z, as.w + ad.w};
    float4 ex;
    float* exp_ = &ex.x;
    #pragma unroll
    for (int h = 0; h < 4; h++) {
        float t = v[h] > 0.f ? v[h] : NEG_SLOPE * v[h];
        exp_[h] = __expf(t);
        atomicAdd(&g_d1[d * H1 + h], exp_[h]);
    }
    *(float4*)&g_e1[(long)e * H1] = ex;
}

// warp per edge: alpha-weighted scatter with vector reductions
__global__ __launch_bounds__(256) void edge1_c() {
    int e = (blockIdx.x * blockDim.x + threadIdx.x) >> 5;
    int lane = threadIdx.x & 31;
    if (e >= E_TOT) return;
    int s = g_src[e], d = g_dst[e];
    float4 ex = *(const float4*)&g_e1[(long)e * H1];
    float4 dn = *(const float4*)&g_d1[d * H1];
    float al0 = ex.x / (dn.x + EPSV);
    float al1 = ex.y / (dn.y + EPSV);
    float al2 = ex.z / (dn.z + EPSV);
    float al3 = ex.w / (dn.w + EPSV);
    const float4* hs = (const float4*)&g_h1[(long)s * F1];
    float* od = &g_out1[(long)d * F1];
    #pragma unroll
    for (int j = 0; j < 2; j++) {
        int i4 = lane + j * 32;                 // float4 index within 256 floats
        float a = (lane < 16) ? (j ? al2 : al0) : (j ? al3 : al1);
        float4 hv = hs[i4];
        hv.x *= a; hv.y *= a; hv.z *= a; hv.w *= a;
        red_add_v4(od + i4 * 4, hv);
    }
}

// elu(out1 + b1) in place -> becomes layer-2 input
__global__ void elu_bias1(const float* __restrict__ b1) {
    int idx = blockIdx.x * blockDim.x + threadIdx.x;
    if (idx >= N_NODES * F1) return;
    float v = g_out1[idx] + b1[idx & (F1 - 1)];
    g_out1[idx] = eluf(v);
}

// ---------------- layer-2 edge passes (H=1) ----------------
__global__ void edge2_ab() {
    int e = blockIdx.x * blockDim.x + threadIdx.x;
    if (e >= E_TOT) return;
    int s = g_src[e], d = g_dst[e];
    float v = g_as2[s] + g_ad2[d];
    v = v > 0.f ? v : NEG_SLOPE * v;
    float ex = __expf(v);
    g_e2[e] = ex;
    atomicAdd(&g_d2[d], ex);
}

// 16 lanes per edge (C2=64 -> 16 float4)
__global__ __launch_bounds__(256) void edge2_c() {
    int e = (blockIdx.x * blockDim.x + threadIdx.x) >> 4;
    int lane = threadIdx.x & 15;
    if (e >= E_TOT) return;
    int s = g_src[e], d = g_dst[e];
    float al = g_e2[e] / (g_d2[d] + EPSV);
    const float4* hs = (const float4*)&g_h2[(long)s * C2];
    float* od = &g_out2[(long)d * C2];
    float4 hv = hs[lane];
    hv.x *= al; hv.y *= al; hv.z *= al; hv.w *= al;
    red_add_v4(od + lane * 4, hv);
}

// ---------------- final: elu(out2+b2) @ Wout + bout ----------------
__global__ void final_kernel(const float* __restrict__ b2,
                             const float* __restrict__ Wout,
                             const float* __restrict__ bout,
                             float* __restrict__ out) {
    int n = blockIdx.x * blockDim.x + threadIdx.x;
    if (n >= N_NODES) return;
    float acc0 = bout[0], acc1 = bout[1], acc2 = bout[2];
    const float* op = &g_out2[(long)n * C2];
    #pragma unroll
    for (int c = 0; c < C2; c++) {
        float v = eluf(op[c] + b2[c]);
        acc0 = fmaf(v, Wout[c * 3 + 0], acc0);
        acc1 = fmaf(v, Wout[c * 3 + 1], acc1);
        acc2 = fmaf(v, Wout[c * 3 + 2], acc2);
    }
    out[n * 3 + 0] = acc0;
    out[n * 3 + 1] = acc1;
    out[n * 3 + 2] = acc2;
}

// ---------------- launch ----------------
extern "C" void kernel_launch(void* const* d_in, const int* in_sizes, int n_in,
                              void* d_out, int out_size) {
    const float* x        = (const float*)d_in[0];
    const void*  ei       = d_in[1];
    const float* W1       = (const float*)d_in[2];
    const float* att_src1 = (const float*)d_in[3];
    const float* att_dst1 = (const float*)d_in[4];
    const float* b1       = (const float*)d_in[5];
    const float* W2       = (const float*)d_in[6];
    const float* att_src2 = (const float*)d_in[7];
    const float* att_dst2 = (const float*)d_in[8];
    const float* b2       = (const float*)d_in[9];
    const float* Wout     = (const float*)d_in[10];
    const float* bout     = (const float*)d_in[11];
    float* out = (float*)d_out;

    float *p_h1, *p_out1, *p_h2;
    cudaGetSymbolAddress((void**)&p_h1,   g_h1);
    cudaGetSymbolAddress((void**)&p_out1, g_out1);
    cudaGetSymbolAddress((void**)&p_h2,   g_h2);

    const int T = 256;

    detect_kernel<<<1, 32>>>((const unsigned int*)ei);
    convert_kernel<<<(E_TOT + T - 1) / T, T>>>(ei);
    init_kernel<<<(N_NODES * F1 + T - 1) / T, T>>>();

    // layer 1
    {
        dim3 grid(F1 / GBN, (N_NODES + GBM - 1) / GBM);
        gemm_kernel<<<grid, 256>>>(x, W1, p_h1, N_NODES, IN_DIM, F1);
    }
    attscore1_kernel<<<(N_NODES * H1 + T - 1) / T, T>>>(att_src1, att_dst1);
    edge1_ab<<<(E_TOT + T - 1) / T, T>>>();
    edge1_c<<<(E_TOT * 32 + T - 1) / T, T>>>();
    elu_bias1<<<(N_NODES * F1 + T - 1) / T, T>>>(b1);

    // layer 2
    {
        dim3 grid(C2 / GBN, (N_NODES + GBM - 1) / GBM);
        gemm_kernel<<<grid, 256>>>(p_out1, W2, p_h2, N_NODES, F1, C2);
    }
    attscore2_kernel<<<(N_NODES + T - 1) / T, T>>>(att_src2, att_dst2);
    edge2_ab<<<(E_TOT + T - 1) / T, T>>>();
    edge2_c<<<(E_TOT * 16 + T - 1) / T, T>>>();

    final_kernel<<<(N_NODES + T - 1) / T, T>>>(b2, Wout, bout, out);
}

// round 5
// speedup vs baseline: 2.2373x; 1.5185x over previous
#include <cuda_runtime.h>
#include <math.h>
#include <stdint.h>

#define N_NODES 50000
#define E_RAW   400000
#define E_TOT   (E_RAW + N_NODES)   // 450000 with self loops
#define IN_DIM  128
#define H1      4
#define C1      64
#define F1      256                 // H1*C1
#define C2      64
#define OUT_DIM 3
#define NEG_SLOPE 0.2f
#define EPSV    1e-16f
#define NB_SCAN ((N_NODES + 255) / 256)   // 196 scan blocks

// ---------------- scratch (static device globals; no allocation) ----------------
__device__ __align__(16) float g_h1[N_NODES * F1];    // x @ W1
__device__ __align__(16) float g_out1[N_NODES * F1];  // elu(agg1 + b1) -> layer-2 input
__device__ __align__(16) float g_as1[N_NODES * H1];
__device__ __align__(16) float g_ad1[N_NODES * H1];
__device__ __align__(16) float g_e1[E_TOT * H1];      // exp scores, CSR order

__device__ __align__(16) float g_h2[N_NODES * C2];    // layer-2 linear
__device__ float g_as2[N_NODES];
__device__ float g_ad2[N_NODES];
__device__ float g_e2[E_TOT];                          // exp scores, CSR order

__device__ int g_src[E_TOT];
__device__ int g_dst[E_TOT];
__device__ int g_cnt[N_NODES];       // in-degree (incl self loop)
__device__ int g_row[N_NODES];       // CSR row start (exclusive scan of cnt)
__device__ int g_fill[N_NODES];
__device__ int g_bsum[NB_SCAN];
__device__ int g_boff[NB_SCAN];
__device__ int g_csr_src[E_TOT];     // src node per CSR slot
__device__ int g_is64;

// ---------------- helpers ----------------
__device__ __forceinline__ float eluf(float x) {
    return x > 0.f ? x : expm1f(x);
}

// ---------------- edge index dtype detect + convert ----------------
__global__ void detect_kernel(const unsigned int* __restrict__ ei32) {
    if (threadIdx.x == 0 && blockIdx.x == 0) {
        unsigned int ornz = 0;
        #pragma unroll
        for (int i = 0; i < 64; i++) ornz |= ei32[2 * i + 1];
        g_is64 = (ornz == 0u) ? 1 : 0;
    }
}

__global__ void convert_kernel(const void* __restrict__ ei) {
    int e = blockIdx.x * blockDim.x + threadIdx.x;
    if (e < N_NODES) { g_cnt[e] = 0; g_fill[e] = 0; }
    if (e >= E_TOT) return;
    if (e >= E_RAW) { g_src[e] = g_dst[e] = e - E_RAW; return; }
    if (g_is64) {
        const long long* p = (const long long*)ei;
        g_src[e] = (int)p[e];
        g_dst[e] = (int)p[E_RAW + e];
    } else {
        const int* p = (const int*)ei;
        g_src[e] = p[e];
        g_dst[e] = p[E_RAW + e];
    }
}

// ---------------- CSR build ----------------
__global__ void count_kernel() {
    int e = blockIdx.x * blockDim.x + threadIdx.x;
    if (e >= E_TOT) return;
    atomicAdd(&g_cnt[g_dst[e]], 1);
}

// per-block exclusive scan of cnt (256 wide), block sums out
__global__ void scan1_kernel() {
    __shared__ int sm[256];
    int tid = threadIdx.x;
    int gid = blockIdx.x * 256 + tid;
    int v = (gid < N_NODES) ? g_cnt[gid] : 0;
    sm[tid] = v;
    __syncthreads();
    #pragma unroll
    for (int off = 1; off < 256; off <<= 1) {
        int t = (tid >= off) ? sm[tid - off] : 0;
        __syncthreads();
        sm[tid] += t;
        __syncthreads();
    }
    if (gid < N_NODES) g_row[gid] = sm[tid] - v;   // exclusive within block
    if (tid == 255) g_bsum[blockIdx.x] = sm[255];
}

__global__ void scan2_kernel() {   // single block, scan 196 block sums
    __shared__ int sm[256];
    int tid = threadIdx.x;
    int v = (tid < NB_SCAN) ? g_bsum[tid] : 0;
    sm[tid] = v;
    __syncthreads();
    #pragma unroll
    for (int off = 1; off < 256; off <<= 1) {
        int t = (tid >= off) ? sm[tid - off] : 0;
        __syncthreads();
        sm[tid] += t;
        __syncthreads();
    }
    if (tid < NB_SCAN) g_boff[tid] = sm[tid] - v;  // exclusive
}

__global__ void scan3_kernel() {
    int gid = blockIdx.x * 256 + threadIdx.x;
    if (gid < N_NODES) g_row[gid] += g_boff[blockIdx.x];
}

__global__ void scatter_kernel() {
    int e = blockIdx.x * blockDim.x + threadIdx.x;
    if (e >= E_TOT) return;
    int d = g_dst[e];
    int pos = g_row[d] + atomicAdd(&g_fill[d], 1);
    g_csr_src[pos] = g_src[e];
}

// ---------------- tiled GEMM: C[M,N] = A[M,K] @ B[K,N] ----------------
#define GBM 128
#define GBN 64
#define GBK 16
__global__ __launch_bounds__(256) void gemm_kernel(const float* __restrict__ A,
                                                   const float* __restrict__ B,
                                                   float* __restrict__ C,
                                                   int M, int K, int N) {
    __shared__ float As[GBK][GBM];
    __shared__ float Bs[GBK][GBN];
    const int tid = threadIdx.x;
    const int tx = tid & 15;
    const int ty = tid >> 4;
    const int by = blockIdx.y * GBM, bx = blockIdx.x * GBN;

    float acc[8][4] = {};
    for (int k0 = 0; k0 < K; k0 += GBK) {
        #pragma unroll
        for (int i = 0; i < 2; i++) {
            int idx = tid + i * 256;
            int r = idx >> 2, c4 = (idx & 3) * 4;
            int row = by + r;
            float4 v = make_float4(0.f, 0.f, 0.f, 0.f);
            if (row < M) v = *(const float4*)&A[(long)row * K + k0 + c4];
            As[c4 + 0][r] = v.x;
            As[c4 + 1][r] = v.y;
            As[c4 + 2][r] = v.z;
            As[c4 + 3][r] = v.w;
        }
        {
            int r = tid >> 4, c4 = (tid & 15) * 4;
            *(float4*)&Bs[r][c4] = *(const float4*)&B[(long)(k0 + r) * N + bx + c4];
        }
        __syncthreads();
        #pragma unroll
        for (int kk = 0; kk < GBK; kk++) {
            float4 a0 = *(const float4*)&As[kk][ty * 8];
            float4 a1 = *(const float4*)&As[kk][ty * 8 + 4];
            float4 b  = *(const float4*)&Bs[kk][tx * 4];
            float a[8] = {a0.x, a0.y, a0.z, a0.w, a1.x, a1.y, a1.z, a1.w};
            float bb[4] = {b.x, b.y, b.z, b.w};
            #pragma unroll
            for (int m = 0; m < 8; m++)
                #pragma unroll
                for (int n = 0; n < 4; n++)
                    acc[m][n] = fmaf(a[m], bb[n], acc[m][n]);
        }
        __syncthreads();
    }
    #pragma unroll
    for (int m = 0; m < 8; m++) {
        int row = by + ty * 8 + m;
        if (row < M) {
            float4 v = make_float4(acc[m][0], acc[m][1], acc[m][2], acc[m][3]);
            *(float4*)&C[(long)row * N + bx + tx * 4] = v;
        }
    }
}

// ---------------- attention scores ----------------
__global__ void attscore1_kernel(const float* __restrict__ att_src,
                                 const float* __restrict__ att_dst) {
    int idx = blockIdx.x * blockDim.x + threadIdx.x;
    if (idx >= N_NODES * H1) return;
    int n = idx / H1, h = idx % H1;
    const float* hp = &g_h1[(long)n * F1 + h * C1];
    float s = 0.f, d = 0.f;
    #pragma unroll
    for (int c = 0; c < C1; c++) {
        float v = hp[c];
        s = fmaf(v, att_src[h * C1 + c], s);
        d = fmaf(v, att_dst[h * C1 + c], d);
    }
    g_as1[idx] = s;
    g_ad1[idx] = d;
}

__global__ void attscore2_kernel(const float* __restrict__ att_src,
                                 const float* __restrict__ att_dst) {
    int n = blockIdx.x * blockDim.x + threadIdx.x;
    if (n >= N_NODES) return;
    const float* hp = &g_h2[(long)n * C2];
    float s = 0.f, d = 0.f;
    #pragma unroll
    for (int c = 0; c < C2; c++) {
        float v = hp[c];
        s = fmaf(v, att_src[c], s);
        d = fmaf(v, att_dst[c], d);
    }
    g_as2[n] = s;
    g_ad2[n] = d;
}

// ---------------- layer 1: fused softmax + aggregation + bias + elu ----------------
// one warp per dst node; lane owns cols [lane*8, lane*8+8)
__global__ __launch_bounds__(256) void agg1_kernel(const float* __restrict__ b1) {
    int w = (blockIdx.x * blockDim.x + threadIdx.x) >> 5;
    int lane = threadIdx.x & 31;
    if (w >= N_NODES) return;
    int start = g_row[w];
    int end = start + g_cnt[w];

    float4 ad = *(const float4*)&g_ad1[w * H1];
    float4 den = make_float4(0.f, 0.f, 0.f, 0.f);
    for (int i = start + lane; i < end; i += 32) {
        int s = g_csr_src[i];
        float4 as = *(const float4*)&g_as1[s * H1];
        float4 v;
        v.x = as.x + ad.x; v.y = as.y + ad.y; v.z = as.z + ad.z; v.w = as.w + ad.w;
        v.x = __expf(v.x > 0.f ? v.x : NEG_SLOPE * v.x);
        v.y = __expf(v.y > 0.f ? v.y : NEG_SLOPE * v.y);
        v.z = __expf(v.z > 0.f ? v.z : NEG_SLOPE * v.z);
        v.w = __expf(v.w > 0.f ? v.w : NEG_SLOPE * v.w);
        *(float4*)&g_e1[(long)i * H1] = v;
        den.x += v.x; den.y += v.y; den.z += v.z; den.w += v.w;
    }
    #pragma unroll
    for (int o = 16; o; o >>= 1) {
        den.x += __shfl_xor_sync(0xffffffffu, den.x, o);
        den.y += __shfl_xor_sync(0xffffffffu, den.y, o);
        den.z += __shfl_xor_sync(0xffffffffu, den.z, o);
        den.w += __shfl_xor_sync(0xffffffffu, den.w, o);
    }
    int h = lane >> 3;
    float denh = (h == 0) ? den.x : (h == 1) ? den.y : (h == 2) ? den.z : den.w;
    float inv = 1.f / (denh + EPSV);

    float4 acc0 = make_float4(0.f, 0.f, 0.f, 0.f);
    float4 acc1 = make_float4(0.f, 0.f, 0.f, 0.f);
    for (int i = start; i < end; i++) {
        int s = g_csr_src[i];
        float4 e4 = *(const float4*)&g_e1[(long)i * H1];
        float a = ((h == 0) ? e4.x : (h == 1) ? e4.y : (h == 2) ? e4.z : e4.w) * inv;
        const float4* hp = (const float4*)&g_h1[(long)s * F1 + lane * 8];
        float4 h0 = hp[0], h1v = hp[1];
        acc0.x = fmaf(a, h0.x, acc0.x);  acc0.y = fmaf(a, h0.y, acc0.y);
        acc0.z = fmaf(a, h0.z, acc0.z);  acc0.w = fmaf(a, h0.w, acc0.w);
        acc1.x = fmaf(a, h1v.x, acc1.x); acc1.y = fmaf(a, h1v.y, acc1.y);
        acc1.z = fmaf(a, h1v.z, acc1.z); acc1.w = fmaf(a, h1v.w, acc1.w);
    }
    int cb = lane * 8;
    float4 bb0 = *(const float4*)&b1[cb];
    float4 bb1 = *(const float4*)&b1[cb + 4];
    acc0.x = eluf(acc0.x + bb0.x); acc0.y = eluf(acc0.y + bb0.y);
    acc0.z = eluf(acc0.z + bb0.z); acc0.w = eluf(acc0.w + bb0.w);
    acc1.x = eluf(acc1.x + bb1.x); acc1.y = eluf(acc1.y + bb1.y);
    acc1.z = eluf(acc1.z + bb1.z); acc1.w = eluf(acc1.w + bb1.w);
    float4* op = (float4*)&g_out1[(long)w * F1 + cb];
    op[0] = acc0;
    op[1] = acc1;
}

// ---------------- layer 2: fused softmax + aggregation + bias + elu + output head ----
// one warp per dst node; lane owns cols [lane*2, lane*2+2)
__global__ __launch_bounds__(256) void agg2_kernel(const float* __restrict__ b2,
                                                   const float* __restrict__ Wout,
                                                   const float* __restrict__ bout,
                                                   float* __restrict__ out) {
    int w = (blockIdx.x * blockDim.x + threadIdx.x) >> 5;
    int lane = threadIdx.x & 31;
    if (w >= N_NODES) return;
    int start = g_row[w];
    int end = start + g_cnt[w];

    float ad = g_ad2[w];
    float den = 0.f;
    for (int i = start + lane; i < end; i += 32) {
        int s = g_csr_src[i];
        float v = g_as2[s] + ad;
        v = v > 0.f ? v : NEG_SLOPE * v;
        float ex = __expf(v);
        g_e2[i] = ex;
        den += ex;
    }
    #pragma unroll
    for (int o = 16; o; o >>= 1) den += __shfl_xor_sync(0xffffffffu, den, o);
    float inv = 1.f / (den + EPSV);

    int c0 = lane * 2;
    float acc0 = 0.f, acc1 = 0.f;
    for (int i = start; i < end; i++) {
        int s = g_csr_src[i];
        float a = g_e2[i] * inv;
        float2 hv = *(const float2*)&g_h2[(long)s * C2 + c0];
        acc0 = fmaf(a, hv.x, acc0);
        acc1 = fmaf(a, hv.y, acc1);
    }
    float v0 = eluf(acc0 + b2[c0]);
    float v1 = eluf(acc1 + b2[c0 + 1]);
    float p0 = fmaf(v0, Wout[c0 * 3 + 0], v1 * Wout[(c0 + 1) * 3 + 0]);
    float p1 = fmaf(v0, Wout[c0 * 3 + 1], v1 * Wout[(c0 + 1) * 3 + 1]);
    float p2 = fmaf(v0, Wout[c0 * 3 + 2], v1 * Wout[(c0 + 1) * 3 + 2]);
    #pragma unroll
    for (int o = 16; o; o >>= 1) {
        p0 += __shfl_xor_sync(0xffffffffu, p0, o);
        p1 += __shfl_xor_sync(0xffffffffu, p1, o);
        p2 += __shfl_xor_sync(0xffffffffu, p2, o);
    }
    if (lane == 0) {
        out[w * 3 + 0] = p0 + bout[0];
        out[w * 3 + 1] = p1 + bout[1];
        out[w * 3 + 2] = p2 + bout[2];
    }
}

// ---------------- launch ----------------
extern "C" void kernel_launch(void* const* d_in, const int* in_sizes, int n_in,
                              void* d_out, int out_size) {
    const float* x        = (const float*)d_in[0];
    const void*  ei       = d_in[1];
    const float* W1       = (const float*)d_in[2];
    const float* att_src1 = (const float*)d_in[3];
    const float* att_dst1 = (const float*)d_in[4];
    const float* b1       = (const float*)d_in[5];
    const float* W2       = (const float*)d_in[6];
    const float* att_src2 = (const float*)d_in[7];
    const float* att_dst2 = (const float*)d_in[8];
    const float* b2       = (const float*)d_in[9];
    const float* Wout     = (const float*)d_in[10];
    const float* bout     = (const float*)d_in[11];
    float* out = (float*)d_out;

    float *p_h1, *p_out1, *p_h2;
    cudaGetSymbolAddress((void**)&p_h1,   g_h1);
    cudaGetSymbolAddress((void**)&p_out1, g_out1);
    cudaGetSymbolAddress((void**)&p_h2,   g_h2);

    const int T = 256;
    const int EB = (E_TOT + T - 1) / T;

    // edge list -> int32 + CSR
    detect_kernel<<<1, 32>>>((const unsigned int*)ei);
    convert_kernel<<<EB, T>>>(ei);
    count_kernel<<<EB, T>>>();
    scan1_kernel<<<NB_SCAN, 256>>>();
    scan2_kernel<<<1, 256>>>();
    scan3_kernel<<<NB_SCAN, 256>>>();
    scatter_kernel<<<EB, T>>>();

    // layer 1
    {
        dim3 grid(F1 / GBN, (N_NODES + GBM - 1) / GBM);
        gemm_kernel<<<grid, 256>>>(x, W1, p_h1, N_NODES, IN_DIM, F1);
    }
    attscore1_kernel<<<(N_NODES * H1 + T - 1) / T, T>>>(att_src1, att_dst1);
    agg1_kernel<<<(N_NODES * 32 + T - 1) / T, T>>>(b1);

    // layer 2
    {
        dim3 grid(C2 / GBN, (N_NODES + GBM - 1) / GBM);
        gemm_kernel<<<grid, 256>>>(p_out1, W2, p_h2, N_NODES, F1, C2);
    }
    attscore2_kernel<<<(N_NODES + T - 1) / T, T>>>(att_src2, att_dst2);
    agg2_kernel<<<(N_NODES * 32 + T - 1) / T, T>>>(b2, Wout, bout, out);
}

// round 6
// speedup vs baseline: 2.4172x; 1.0804x over previous
#include <cuda_runtime.h>
#include <math.h>
#include <stdint.h>

#define N_NODES 50000
#define E_RAW   400000
#define E_TOT   (E_RAW + N_NODES)   // 450000 with self loops
#define IN_DIM  128
#define H1      4
#define C1      64
#define F1      256                 // H1*C1
#define C2      64
#define OUT_DIM 3
#define NEG_SLOPE 0.2f
#define EPSV    1e-16f
#define NB_SCAN ((N_NODES + 255) / 256)   // 196 scan blocks

// ---------------- scratch (static device globals; no allocation) ----------------
__device__ __align__(16) float g_h1[N_NODES * F1];    // x @ W1
__device__ __align__(16) float g_out1[N_NODES * F1];  // elu(agg1 + b1) -> layer-2 input
__device__ __align__(16) float g_as1[N_NODES * H1];
__device__ __align__(16) float g_ad1[N_NODES * H1];
__device__ __align__(16) float g_e1[E_TOT * H1];      // exp scores, CSR order

__device__ __align__(16) float g_h2[N_NODES * C2];    // layer-2 linear
__device__ float g_as2[N_NODES];
__device__ float g_ad2[N_NODES];
__device__ float g_e2[E_TOT];                          // exp scores, CSR order

__device__ int g_cnt[N_NODES];       // in-degree (incl self loop)
__device__ int g_row[N_NODES];       // CSR row start
__device__ int g_fill[N_NODES];
__device__ int g_bsum[NB_SCAN];
__device__ int g_boff[NB_SCAN];
__device__ int g_csr_src[E_TOT];     // src node per CSR slot
__device__ int g_is64;

// ---------------- helpers ----------------
__device__ __forceinline__ float eluf(float x) {
    return x > 0.f ? x : expm1f(x);
}

__device__ __forceinline__ void load_edge(const void* ei, int e, int& s, int& d) {
    if (e >= E_RAW) { s = d = e - E_RAW; return; }
    if (g_is64) {
        const long long* p = (const long long*)ei;
        s = (int)p[e];
        d = (int)p[E_RAW + e];
    } else {
        const int* p = (const int*)ei;
        s = p[e];
        d = p[E_RAW + e];
    }
}

// ---------------- edge index dtype detect ----------------
__global__ void detect_kernel(const unsigned int* __restrict__ ei32) {
    if (threadIdx.x == 0 && blockIdx.x == 0) {
        unsigned int ornz = 0;
        #pragma unroll
        for (int i = 0; i < 64; i++) ornz |= ei32[2 * i + 1];
        g_is64 = (ornz == 0u) ? 1 : 0;
    }
}

// ---------------- CSR build ----------------
__global__ void zero_kernel() {
    int n = blockIdx.x * blockDim.x + threadIdx.x;
    if (n < N_NODES) { g_cnt[n] = 0; g_fill[n] = 0; }
}

__global__ void count_kernel(const void* __restrict__ ei) {
    int e = blockIdx.x * blockDim.x + threadIdx.x;
    if (e >= E_TOT) return;
    int s, d; load_edge(ei, e, s, d);
    atomicAdd(&g_cnt[d], 1);
}

__global__ void scan1_kernel() {
    __shared__ int sm[256];
    int tid = threadIdx.x;
    int gid = blockIdx.x * 256 + tid;
    int v = (gid < N_NODES) ? g_cnt[gid] : 0;
    sm[tid] = v;
    __syncthreads();
    #pragma unroll
    for (int off = 1; off < 256; off <<= 1) {
        int t = (tid >= off) ? sm[tid - off] : 0;
        __syncthreads();
        sm[tid] += t;
        __syncthreads();
    }
    if (gid < N_NODES) g_row[gid] = sm[tid] - v;
    if (tid == 255) g_bsum[blockIdx.x] = sm[255];
}

__global__ void scan2_kernel() {
    __shared__ int sm[256];
    int tid = threadIdx.x;
    int v = (tid < NB_SCAN) ? g_bsum[tid] : 0;
    sm[tid] = v;
    __syncthreads();
    #pragma unroll
    for (int off = 1; off < 256; off <<= 1) {
        int t = (tid >= off) ? sm[tid - off] : 0;
        __syncthreads();
        sm[tid] += t;
        __syncthreads();
    }
    if (tid < NB_SCAN) g_boff[tid] = sm[tid] - v;
}

__global__ void scan3_kernel() {
    int gid = blockIdx.x * 256 + threadIdx.x;
    if (gid < N_NODES) g_row[gid] += g_boff[blockIdx.x];
}

__global__ void scatter_kernel(const void* __restrict__ ei) {
    int e = blockIdx.x * blockDim.x + threadIdx.x;
    if (e >= E_TOT) return;
    int s, d; load_edge(ei, e, s, d);
    int pos = g_row[d] + atomicAdd(&g_fill[d], 1);
    g_csr_src[pos] = s;
}

// ---------------- GEMM + fused attention scores ----------------
// C[M,N] = A[M,K] @ B[K,N]; also as_out[row,h] = sum_c C[row, h*64+c]*att_src[h*64+c]
// BM=128, BK=16, 256 threads (16x16), microtile 8 x TN. NH = BN/64 heads per block.
template<int BN, int TN, int NH>
__global__ __launch_bounds__(256, 2) void gemm_att_kernel(
    const float* __restrict__ A, const float* __restrict__ B, float* __restrict__ C,
    const float* __restrict__ att_src, const float* __restrict__ att_dst,
    float* __restrict__ as_out, float* __restrict__ ad_out,
    int M, int K, int N, int HTOT)
{
    __shared__ float As[16][128];
    __shared__ float Bs[16][BN];
    const int tid = threadIdx.x;
    const int tx = tid & 15;
    const int ty = tid >> 4;
    const int by = blockIdx.y * 128, bx = blockIdx.x * BN;

    float acc[8][TN];
    #pragma unroll
    for (int m = 0; m < 8; m++)
        #pragma unroll
        for (int n = 0; n < TN; n++) acc[m][n] = 0.f;

    for (int k0 = 0; k0 < K; k0 += 16) {
        // A tile: 128x16 = 512 float4, 2 per thread (transposed store)
        #pragma unroll
        for (int i = 0; i < 2; i++) {
            int idx = tid + i * 256;
            int r = idx >> 2, c4 = (idx & 3) * 4;
            int row = by + r;
            float4 v = make_float4(0.f, 0.f, 0.f, 0.f);
            if (row < M) v = *(const float4*)&A[(long)row * K + k0 + c4];
            As[c4 + 0][r] = v.x;
            As[c4 + 1][r] = v.y;
            As[c4 + 2][r] = v.z;
            As[c4 + 3][r] = v.w;
        }
        // B tile: 16 x BN = 4*BN float4, BN/64 per thread
        #pragma unroll
        for (int i = 0; i < BN / 64; i++) {
            int idx = tid + i * 256;
            int r = idx / (BN / 4), c4 = (idx % (BN / 4)) * 4;
            *(float4*)&Bs[r][c4] = *(const float4*)&B[(long)(k0 + r) * N + bx + c4];
        }
        __syncthreads();
        #pragma unroll
        for (int kk = 0; kk < 16; kk++) {
            float a[8], b[TN];
            #pragma unroll
            for (int m = 0; m < 8; m++) a[m] = As[kk][ty * 8 + m];
            #pragma unroll
            for (int n = 0; n < TN; n++) b[n] = Bs[kk][tx * TN + n];
            #pragma unroll
            for (int m = 0; m < 8; m++)
                #pragma unroll
                for (int n = 0; n < TN; n++)
                    acc[m][n] = fmaf(a[m], b[n], acc[m][n]);
        }
        __syncthreads();
    }

    // store C
    #pragma unroll
    for (int m = 0; m < 8; m++) {
        int row = by + ty * 8 + m;
        if (row < M) {
            #pragma unroll
            for (int n4 = 0; n4 < TN / 4; n4++) {
                float4 v = make_float4(acc[m][n4 * 4 + 0], acc[m][n4 * 4 + 1],
                                       acc[m][n4 * 4 + 2], acc[m][n4 * 4 + 3]);
                *(float4*)&C[(long)row * N + bx + tx * TN + n4 * 4] = v;
            }
        }
    }

    // fused attention partials: zero-padded rows give zero partials (As zero-fill)
    float att_s[TN], att_d[TN];
    #pragma unroll
    for (int n = 0; n < TN; n++) {
        int col = bx + tx * TN + n;
        att_s[n] = att_src[col];
        att_d[n] = att_dst[col];
    }
    #pragma unroll
    for (int m = 0; m < 8; m++) {
        float s = 0.f, d = 0.f;
        #pragma unroll
        for (int n = 0; n < TN; n++) {
            s = fmaf(acc[m][n], att_s[n], s);
            d = fmaf(acc[m][n], att_d[n], d);
        }
        // reduce over 8-lane tx groups (lanes within warp align with tx groups)
        #pragma unroll
        for (int o = 4; o; o >>= 1) {
            s += __shfl_down_sync(0xffffffffu, s, o, 8);
            d += __shfl_down_sync(0xffffffffu, d, o, 8);
        }
        if (NH == 1) {
            // combine the two 8-lane groups (tx 0..7 and 8..15)
            s += __shfl_down_sync(0xffffffffu, s, 8, 16);
            d += __shfl_down_sync(0xffffffffu, d, 8, 16);
            if (tx == 0) {
                int row = by + ty * 8 + m;
                if (row < M) {
                    int head = bx / 64;
                    as_out[row * HTOT + head] = s;
                    ad_out[row * HTOT + head] = d;
                }
            }
        } else {
            if ((tx & 7) == 0) {
                int row = by + ty * 8 + m;
                if (row < M) {
                    int head = (bx + tx * TN) / 64;
                    as_out[row * HTOT + head] = s;
                    ad_out[row * HTOT + head] = d;
                }
            }
        }
    }
}

// ---------------- layer 1: fused softmax + aggregation + bias + elu ----------------
// one warp per dst node; lane owns cols [lane*8, lane*8+8)
__global__ __launch_bounds__(256) void agg1_kernel(const float* __restrict__ b1) {
    int w = (blockIdx.x * blockDim.x + threadIdx.x) >> 5;
    int lane = threadIdx.x & 31;
    if (w >= N_NODES) return;
    int start = g_row[w];
    int end = start + g_cnt[w];

    float4 ad = *(const float4*)&g_ad1[w * H1];
    float4 den = make_float4(0.f, 0.f, 0.f, 0.f);
    for (int i = start + lane; i < end; i += 32) {
        int s = g_csr_src[i];
        float4 as = *(const float4*)&g_as1[s * H1];
        float4 v;
        v.x = as.x + ad.x; v.y = as.y + ad.y; v.z = as.z + ad.z; v.w = as.w + ad.w;
        v.x = __expf(v.x > 0.f ? v.x : NEG_SLOPE * v.x);
        v.y = __expf(v.y > 0.f ? v.y : NEG_SLOPE * v.y);
        v.z = __expf(v.z > 0.f ? v.z : NEG_SLOPE * v.z);
        v.w = __expf(v.w > 0.f ? v.w : NEG_SLOPE * v.w);
        *(float4*)&g_e1[(long)i * H1] = v;
        den.x += v.x; den.y += v.y; den.z += v.z; den.w += v.w;
    }
    #pragma unroll
    for (int o = 16; o; o >>= 1) {
        den.x += __shfl_xor_sync(0xffffffffu, den.x, o);
        den.y += __shfl_xor_sync(0xffffffffu, den.y, o);
        den.z += __shfl_xor_sync(0xffffffffu, den.z, o);
        den.w += __shfl_xor_sync(0xffffffffu, den.w, o);
    }
    int h = lane >> 3;
    float denh = (h == 0) ? den.x : (h == 1) ? den.y : (h == 2) ? den.z : den.w;
    float inv = 1.f / (denh + EPSV);

    float4 acc0 = make_float4(0.f, 0.f, 0.f, 0.f);
    float4 acc1 = make_float4(0.f, 0.f, 0.f, 0.f);
    int i = start;
    for (; i + 2 <= end; i += 2) {
        int s0 = g_csr_src[i], s1 = g_csr_src[i + 1];
        float4 e40 = *(const float4*)&g_e1[(long)i * H1];
        float4 e41 = *(const float4*)&g_e1[(long)(i + 1) * H1];
        float a0 = ((h == 0) ? e40.x : (h == 1) ? e40.y : (h == 2) ? e40.z : e40.w) * inv;
        float a1 = ((h == 0) ? e41.x : (h == 1) ? e41.y : (h == 2) ? e41.z : e41.w) * inv;
        const float4* hp0 = (const float4*)&g_h1[(long)s0 * F1 + lane * 8];
        const float4* hp1 = (const float4*)&g_h1[(long)s1 * F1 + lane * 8];
        float4 x0 = hp0[0], x1 = hp0[1];
        float4 y0 = hp1[0], y1 = hp1[1];
        acc0.x = fmaf(a0, x0.x, acc0.x); acc0.y = fmaf(a0, x0.y, acc0.y);
        acc0.z = fmaf(a0, x0.z, acc0.z); acc0.w = fmaf(a0, x0.w, acc0.w);
        acc1.x = fmaf(a0, x1.x, acc1.x); acc1.y = fmaf(a0, x1.y, acc1.y);
        acc1.z = fmaf(a0, x1.z, acc1.z); acc1.w = fmaf(a0, x1.w, acc1.w);
        acc0.x = fmaf(a1, y0.x, acc0.x); acc0.y = fmaf(a1, y0.y, acc0.y);
        acc0.z = fmaf(a1, y0.z, acc0.z); acc0.w = fmaf(a1, y0.w, acc0.w);
        acc1.x = fmaf(a1, y1.x, acc1.x); acc1.y = fmaf(a1, y1.y, acc1.y);
        acc1.z = fmaf(a1, y1.z, acc1.z); acc1.w = fmaf(a1, y1.w, acc1.w);
    }
    if (i < end) {
        int s0 = g_csr_src[i];
        float4 e40 = *(const float4*)&g_e1[(long)i * H1];
        float a0 = ((h == 0) ? e40.x : (h == 1) ? e40.y : (h == 2) ? e40.z : e40.w) * inv;
        const float4* hp0 = (const float4*)&g_h1[(long)s0 * F1 + lane * 8];
        float4 x0 = hp0[0], x1 = hp0[1];
        acc0.x = fmaf(a0, x0.x, acc0.x); acc0.y = fmaf(a0, x0.y, acc0.y);
        acc0.z = fmaf(a0, x0.z, acc0.z); acc0.w = fmaf(a0, x0.w, acc0.w);
        acc1.x = fmaf(a0, x1.x, acc1.x); acc1.y = fmaf(a0, x1.y, acc1.y);
        acc1.z = fmaf(a0, x1.z, acc1.z); acc1.w = fmaf(a0, x1.w, acc1.w);
    }
    int cb = lane * 8;
    float4 bb0 = *(const float4*)&b1[cb];
    float4 bb1 = *(const float4*)&b1[cb + 4];
    acc0.x = eluf(acc0.x + bb0.x); acc0.y = eluf(acc0.y + bb0.y);
    acc0.z = eluf(acc0.z + bb0.z); acc0.w = eluf(acc0.w + bb0.w);
    acc1.x = eluf(acc1.x + bb1.x); acc1.y = eluf(acc1.y + bb1.y);
    acc1.z = eluf(acc1.z + bb1.z); acc1.w = eluf(acc1.w + bb1.w);
    float4* op = (float4*)&g_out1[(long)w * F1 + cb];
    op[0] = acc0;
    op[1] = acc1;
}

// ---------------- layer 2: fused softmax + aggregation + bias + elu + head ----------
__global__ __launch_bounds__(256) void agg2_kernel(const float* __restrict__ b2,
                                                   const float* __restrict__ Wout,
                                                   const float* __restrict__ bout,
                                                   float* __restrict__ out) {
    int w = (blockIdx.x * blockDim.x + threadIdx.x) >> 5;
    int lane = threadIdx.x & 31;
    if (w >= N_NODES) return;
    int start = g_row[w];
    int end = start + g_cnt[w];

    float ad = g_ad2[w];
    float den = 0.f;
    for (int i = start + lane; i < end; i += 32) {
        int s = g_csr_src[i];
        float v = g_as2[s] + ad;
        v = v > 0.f ? v : NEG_SLOPE * v;
        float ex = __expf(v);
        g_e2[i] = ex;
        den += ex;
    }
    #pragma unroll
    for (int o = 16; o; o >>= 1) den += __shfl_xor_sync(0xffffffffu, den, o);
    float inv = 1.f / (den + EPSV);

    int c0 = lane * 2;
    float acc0 = 0.f, acc1 = 0.f;
    int i = start;
    for (; i + 2 <= end; i += 2) {
        int s0 = g_csr_src[i], s1 = g_csr_src[i + 1];
        float a0 = g_e2[i] * inv, a1 = g_e2[i + 1] * inv;
        float2 h0 = *(const float2*)&g_h2[(long)s0 * C2 + c0];
        float2 h1 = *(const float2*)&g_h2[(long)s1 * C2 + c0];
        acc0 = fmaf(a0, h0.x, acc0); acc1 = fmaf(a0, h0.y, acc1);
        acc0 = fmaf(a1, h1.x, acc0); acc1 = fmaf(a1, h1.y, acc1);
    }
    if (i < end) {
        int s0 = g_csr_src[i];
        float a0 = g_e2[i] * inv;
        float2 h0 = *(const float2*)&g_h2[(long)s0 * C2 + c0];
        acc0 = fmaf(a0, h0.x, acc0); acc1 = fmaf(a0, h0.y, acc1);
    }
    float v0 = eluf(acc0 + b2[c0]);
    float v1 = eluf(acc1 + b2[c0 + 1]);
    float p0 = fmaf(v0, Wout[c0 * 3 + 0], v1 * Wout[(c0 + 1) * 3 + 0]);
    float p1 = fmaf(v0, Wout[c0 * 3 + 1], v1 * Wout[(c0 + 1) * 3 + 1]);
    float p2 = fmaf(v0, Wout[c0 * 3 + 2], v1 * Wout[(c0 + 1) * 3 + 2]);
    #pragma unroll
    for (int o = 16; o; o >>= 1) {
        p0 += __shfl_xor_sync(0xffffffffu, p0, o);
        p1 += __shfl_xor_sync(0xffffffffu, p1, o);
        p2 += __shfl_xor_sync(0xffffffffu, p2, o);
    }
    if (lane == 0) {
        out[w * 3 + 0] = p0 + bout[0];
        out[w * 3 + 1] = p1 + bout[1];
        out[w * 3 + 2] = p2 + bout[2];
    }
}

// ---------------- launch ----------------
extern "C" void kernel_launch(void* const* d_in, const int* in_sizes, int n_in,
                              void* d_out, int out_size) {
    const float* x        = (const float*)d_in[0];
    const void*  ei       = d_in[1];
    const float* W1       = (const float*)d_in[2];
    const float* att_src1 = (const float*)d_in[3];
    const float* att_dst1 = (const float*)d_in[4];
    const float* b1       = (const float*)d_in[5];
    const float* W2       = (const float*)d_in[6];
    const float* att_src2 = (const float*)d_in[7];
    const float* att_dst2 = (const float*)d_in[8];
    const float* b2       = (const float*)d_in[9];
    const float* Wout     = (const float*)d_in[10];
    const float* bout     = (const float*)d_in[11];
    float* out = (float*)d_out;

    float *p_h1, *p_out1, *p_h2, *p_as1, *p_ad1, *p_as2, *p_ad2;
    cudaGetSymbolAddress((void**)&p_h1,   g_h1);
    cudaGetSymbolAddress((void**)&p_out1, g_out1);
    cudaGetSymbolAddress((void**)&p_h2,   g_h2);
    cudaGetSymbolAddress((void**)&p_as1,  g_as1);
    cudaGetSymbolAddress((void**)&p_ad1,  g_ad1);
    cudaGetSymbolAddress((void**)&p_as2,  g_as2);
    cudaGetSymbolAddress((void**)&p_ad2,  g_ad2);

    const int T = 256;
    const int EB = (E_TOT + T - 1) / T;

    // CSR build
    detect_kernel<<<1, 32>>>((const unsigned int*)ei);
    zero_kernel<<<NB_SCAN, T>>>();
    count_kernel<<<EB, T>>>(ei);
    scan1_kernel<<<NB_SCAN, 256>>>();
    scan2_kernel<<<1, 256>>>();
    scan3_kernel<<<NB_SCAN, 256>>>();
    scatter_kernel<<<EB, T>>>(ei);

    // layer 1: GEMM (+fused attscore), then aggregation
    {
        dim3 grid(F1 / 128, (N_NODES + 127) / 128);
        gemm_att_kernel<128, 8, 2><<<grid, 256>>>(x, W1, p_h1, att_src1, att_dst1,
                                                  p_as1, p_ad1, N_NODES, IN_DIM, F1, H1);
    }
    agg1_kernel<<<(N_NODES * 32 + T - 1) / T, T>>>(b1);

    // layer 2
    {
        dim3 grid(C2 / 64, (N_NODES + 127) / 128);
        gemm_att_kernel<64, 4, 1><<<grid, 256>>>(p_out1, W2, p_h2, att_src2, att_dst2,
                                                 p_as2, p_ad2, N_NODES, F1, C2, 1);
    }
    agg2_kernel<<<(N_NODES * 32 + T - 1) / T, T>>>(b2, Wout, bout, out);
}